// round 16
// baseline (speedup 1.0000x reference)
#include <cuda_runtime.h>
#include <cuda_bf16.h>
#include <cstdint>

// ============================================================================
// kNN (1-NN, L2), round 16: R14 gemm (best measured) + u8 score array
// (halves score store + refine scan traffic) + merged init.
//   prep:   fp32 -> int8 (scale 6.5/127) + exact fp32 s2; prep_x also inits
//           minkey + output canary.
//   gemm:   128x128 tiles, KC=128 int8 (8 chunks), 3-stage cp.async,
//           reg-double-buffered ldmatrix frags, mma.m16n8k32.s8.
//           Epilogue: u8-quantized score (cell 4.0, offset 384) + per-query
//           atomicMin of (q8,idx).
//   refine: scan u8 scores, rows within 6 cells (24 units >= 16-unit noise
//           margin) get exact fp64 decision; overflow -> full fp64 scan.
//   out:    one-hot float32.
// ============================================================================

#define D_DIM   1024
#define M_TOTAL 2048
#define N_REAL  50000
#define N_PAD   50048
#define NTILES  391
#define MTILE   128
#define NTILE   128
#define NUM_MT  (M_TOTAL / MTILE)   // 16
#define KC      128                 // int8 elements per chunk = 128 B rows
#define NUM_KC  (D_DIM / KC)        // 8
#define NSTAGE  3

#define SCALE_Q   (6.5f / 127.0f)
#define SCALE_INV (127.0f / 6.5f)
#define SQ2       (SCALE_Q * SCALE_Q)

#define Q8OFF   384.0f              // u8 score quant: q=(score-384)*0.25
#define Q8SCALE 0.25f
#define QMARGIN 6                   // 24 score units (>= 16-unit noise margin)
#define SEL_CAP 256

#define ROW_B   144                 // 128 B data padded to 144 B
#define TILE_B  (128 * ROW_B)       // 18432
#define STAGE_B (2 * TILE_B)        // 36864
#define SMEM_GEMM (NSTAGE * STAGE_B + 512)   // 111104 B

// ---------------- device-global scratch --------------------------------------
__device__ __align__(16) signed char g_xq[(size_t)M_TOTAL * D_DIM];
__device__ __align__(16) signed char g_sq[(size_t)N_PAD * D_DIM];
__device__ float               g_s2[N_PAD];
__device__ __align__(16) unsigned char g_q8[(size_t)M_TOTAL * N_PAD];  // 102 MB
__device__ unsigned long long  g_minkey[M_TOTAL];
__device__ int                 g_exidx[M_TOTAL];

// ---------------- helpers ----------------------------------------------------
__device__ __forceinline__ uint32_t smem_u32(const void* p) {
    uint32_t a;
    asm("{ .reg .u64 t; cvta.to.shared.u64 t, %1; cvt.u32.u64 %0, t; }"
        : "=r"(a) : "l"(p));
    return a;
}
#define CP_ASYNC16(smem, gptr)                                               \
    asm volatile("cp.async.cg.shared.global [%0], [%1], 16;"                 \
                 :: "r"(smem), "l"(gptr) : "memory")
#define CP_COMMIT() asm volatile("cp.async.commit_group;" ::: "memory")
#define CP_WAIT(n)  asm volatile("cp.async.wait_group %0;" :: "n"(n) : "memory")

__device__ __forceinline__ void ldm_x4(uint32_t& r0, uint32_t& r1,
                                       uint32_t& r2, uint32_t& r3, uint32_t addr) {
    asm volatile("ldmatrix.sync.aligned.m8n8.x4.shared.b16 {%0,%1,%2,%3}, [%4];"
                 : "=r"(r0), "=r"(r1), "=r"(r2), "=r"(r3) : "r"(addr));
}
__device__ __forceinline__ void mma16832(int* c, uint32_t a0, uint32_t a1,
                                         uint32_t a2, uint32_t a3,
                                         uint32_t b0, uint32_t b1) {
    asm volatile(
        "mma.sync.aligned.m16n8k32.row.col.s32.s8.s8.s32 "
        "{%0,%1,%2,%3}, {%4,%5,%6,%7}, {%8,%9}, {%0,%1,%2,%3};"
        : "+r"(c[0]), "+r"(c[1]), "+r"(c[2]), "+r"(c[3])
        : "r"(a0), "r"(a1), "r"(a2), "r"(a3), "r"(b0), "r"(b1));
}
__device__ __forceinline__ unsigned int quant8(float score) {
    float q = (score - Q8OFF) * Q8SCALE;
    q = fminf(fmaxf(q, 0.0f), 255.0f);
    return (unsigned int)__float2uint_rn(q);
}
__device__ __forceinline__ int q8v(float v) {
    int q = __float2int_rn(v * SCALE_INV);
    return max(-127, min(127, q));
}
__device__ __forceinline__ unsigned int pack8(float a, float b, float c, float d) {
    return ((unsigned int)(q8v(a) & 0xFF))       |
           ((unsigned int)(q8v(b) & 0xFF) << 8)  |
           ((unsigned int)(q8v(c) & 0xFF) << 16) |
           ((unsigned int)(q8v(d) & 0xFF) << 24);
}

// ---------------- 1. prep (also inits minkey + output canary) ----------------
__global__ void prep_x_kernel(const float* __restrict__ x,
                              float* __restrict__ out) {
    int row = blockIdx.x;
    int tid = threadIdx.x;              // 256
    float4 v = ((const float4*)(x + (size_t)row * D_DIM))[tid];
    ((unsigned int*)(g_xq + (size_t)row * D_DIM))[tid] = pack8(v.x, v.y, v.z, v.w);
    if (tid == 0) {
        g_minkey[row] = ~0ull;
        out[2 * row + 0] = 7.0f;   // canary
        out[2 * row + 1] = 0.0f;
    }
}

__global__ void prep_support_kernel(const float* __restrict__ sup) {
    int row = blockIdx.x;               // 0..50047
    int tid = threadIdx.x;              // 256
    float acc = 0.0f;
    unsigned int pk = 0;
    if (row < N_REAL) {
        float4 v = ((const float4*)(sup + (size_t)row * D_DIM))[tid];
        acc = v.x * v.x + v.y * v.y + v.z * v.z + v.w * v.w;
        pk = pack8(v.x, v.y, v.z, v.w);
    }
    ((unsigned int*)(g_sq + (size_t)row * D_DIM))[tid] = pk;
    #pragma unroll
    for (int o = 16; o; o >>= 1) acc += __shfl_down_sync(0xffffffffu, acc, o);
    __shared__ float red[8];
    if ((tid & 31) == 0) red[tid >> 5] = acc;
    __syncthreads();
    if (tid == 0) {
        float t = 0.f;
        #pragma unroll
        for (int i = 0; i < 8; i++) t += red[i];
        g_s2[row] = (row < N_REAL) ? t : 3.0e38f;   // pad rows -> q=255
    }
}

// ---------------- 2. GEMM (int8, 3-stage cp.async, 1 barrier/chunk) ----------
__global__ void __launch_bounds__(256, 2) gemm_kernel() {
    extern __shared__ __align__(16) uint8_t sm[];
    float* s2sh = (float*)(sm + NSTAGE * STAGE_B);

    const int tid  = threadIdx.x;
    const int lane = tid & 31;
    const int wid  = tid >> 5;
    const int warp_m = wid & 1;
    const int warp_n = wid >> 1;

    const int mt   = blockIdx.x;
    const int tile = blockIdx.y;
    const int m_base = mt * MTILE;
    const int n_base = tile * NTILE;

    if (tid < NTILE) s2sh[tid] = g_s2[n_base + tid];

    const uint32_t smem_base = smem_u32(sm);

    // cp.async map: 128 rows x 8 16B-cols = 1024 chunks, 4/thread
    const int fr = tid >> 3;            // 0..31 (+32 per p)
    const int fc = tid & 7;
    const uint32_t w_off = (uint32_t)(fr * ROW_B + fc * 16);
    const signed char* gA0 = g_xq + (size_t)(m_base + fr) * D_DIM + fc * 16;
    const signed char* gB0 = g_sq + (size_t)(n_base + fr) * D_DIM + fc * 16;

    auto load_chunk = [&](int stage, int kc) {
        uint32_t sa = smem_base + (uint32_t)(stage * STAGE_B) + w_off;
        uint32_t sb = sa + TILE_B;
        int kb = kc * KC;
        #pragma unroll
        for (int p = 0; p < 4; p++) {
            CP_ASYNC16(sa + (uint32_t)(p * 32 * ROW_B),
                       gA0 + (size_t)(p * 32) * D_DIM + kb);
            CP_ASYNC16(sb + (uint32_t)(p * 32 * ROW_B),
                       gB0 + (size_t)(p * 32) * D_DIM + kb);
        }
    };

    const uint32_t a_lane_off =
        (uint32_t)((lane & 15) * ROW_B + (lane >> 4) * 16);
    const uint32_t b_lane_off =
        (uint32_t)(((((lane >> 4) & 1) * 8 + (lane & 7)) * ROW_B) +
                   (((lane >> 3) & 1) * 16));
    const uint32_t a_warp = (uint32_t)(warp_m * 64 * ROW_B) + a_lane_off;
    const uint32_t b_warp = (uint32_t)(TILE_B + warp_n * 32 * ROW_B) + b_lane_off;

    int acc[4][4][4];
    #pragma unroll
    for (int mi = 0; mi < 4; mi++)
        #pragma unroll
        for (int ni = 0; ni < 4; ni++)
            #pragma unroll
            for (int j = 0; j < 4; j++) acc[mi][ni][j] = 0;

    uint32_t afr[2][4][4];
    uint32_t bfr[2][4][2];

    auto ldfrag = [&](uint32_t a_base, uint32_t b_base, int ks, int slot) {
        #pragma unroll
        for (int mi = 0; mi < 4; mi++)
            ldm_x4(afr[slot][mi][0], afr[slot][mi][1],
                   afr[slot][mi][2], afr[slot][mi][3],
                   a_base + (uint32_t)(mi * 16 * ROW_B + ks * 32));
        #pragma unroll
        for (int nip = 0; nip < 2; nip++) {
            uint32_t r0, r1, r2, r3;
            ldm_x4(r0, r1, r2, r3,
                   b_base + (uint32_t)(nip * 16 * ROW_B + ks * 32));
            bfr[slot][nip * 2][0] = r0;     bfr[slot][nip * 2][1] = r1;
            bfr[slot][nip * 2 + 1][0] = r2; bfr[slot][nip * 2 + 1][1] = r3;
        }
    };

    // prologue: stages 0,1 hold chunks 0,1
    load_chunk(0, 0); CP_COMMIT();
    load_chunk(1, 1); CP_COMMIT();

    int stage = 0;
    for (int kc = 0; kc < NUM_KC; kc++) {
        CP_WAIT(1);          // chunk kc complete (kc+1 may be in flight)
        __syncthreads();     // publishes chunk kc AND retires buffer of kc-1

        if (kc + 2 < NUM_KC) load_chunk((stage + 2) % NSTAGE, kc + 2);
        CP_COMMIT();         // always commit (uniform wait semantics)

        uint32_t a_base = smem_base + (uint32_t)(stage * STAGE_B) + a_warp;
        uint32_t b_base = smem_base + (uint32_t)(stage * STAGE_B) + b_warp;

        ldfrag(a_base, b_base, 0, 0);
        #pragma unroll
        for (int ks = 0; ks < 4; ks++) {   // 4 x k32 = 128 K-elems
            int cur = ks & 1;
            if (ks < 3) ldfrag(a_base, b_base, ks + 1, cur ^ 1);
            #pragma unroll
            for (int mi = 0; mi < 4; mi++)
                #pragma unroll
                for (int ni = 0; ni < 4; ni++)
                    mma16832(acc[mi][ni],
                             afr[cur][mi][0], afr[cur][mi][1],
                             afr[cur][mi][2], afr[cur][mi][3],
                             bfr[cur][ni][0], bfr[cur][ni][1]);
        }
        stage = (stage + 1) % NSTAGE;
    }

    // ---- epilogue: u8 score store + per-row atomicMin ----------------------
    #pragma unroll
    for (int mi = 0; mi < 4; mi++) {
        int r_lo = m_base + warp_m * 64 + mi * 16 + (lane >> 2);
        int r_hi = r_lo + 8;
        unsigned long long k_lo = ~0ull, k_hi = ~0ull;
        #pragma unroll
        for (int ni = 0; ni < 4; ni++) {
            int ncl = warp_n * 32 + ni * 8 + 2 * (lane & 3);
            int ngl = n_base + ncl;
            float s20 = s2sh[ncl], s21 = s2sh[ncl + 1];
            unsigned int q00 = quant8(fmaf(-2.0f * SQ2, (float)acc[mi][ni][0], s20));
            unsigned int q01 = quant8(fmaf(-2.0f * SQ2, (float)acc[mi][ni][1], s21));
            unsigned int q10 = quant8(fmaf(-2.0f * SQ2, (float)acc[mi][ni][2], s20));
            unsigned int q11 = quant8(fmaf(-2.0f * SQ2, (float)acc[mi][ni][3], s21));
            *(unsigned short*)&g_q8[(size_t)r_lo * N_PAD + ngl] =
                (unsigned short)(q00 | (q01 << 8));
            *(unsigned short*)&g_q8[(size_t)r_hi * N_PAD + ngl] =
                (unsigned short)(q10 | (q11 << 8));
            unsigned long long t;
            t = ((unsigned long long)q00 << 32) | (unsigned int)ngl;       if (t < k_lo) k_lo = t;
            t = ((unsigned long long)q01 << 32) | (unsigned int)(ngl + 1); if (t < k_lo) k_lo = t;
            t = ((unsigned long long)q10 << 32) | (unsigned int)ngl;       if (t < k_hi) k_hi = t;
            t = ((unsigned long long)q11 << 32) | (unsigned int)(ngl + 1); if (t < k_hi) k_hi = t;
        }
        #pragma unroll
        for (int m = 1; m <= 2; m <<= 1) {
            unsigned long long o;
            o = __shfl_xor_sync(0xffffffffu, k_lo, m); if (o < k_lo) k_lo = o;
            o = __shfl_xor_sync(0xffffffffu, k_hi, m); if (o < k_hi) k_hi = o;
        }
        if ((lane & 3) == 0) {
            atomicMin(&g_minkey[r_lo], k_lo);
            atomicMin(&g_minkey[r_hi], k_hi);
        }
    }
}

// ---------------- 3. refine: scan u8 scores, fp64 decide ---------------------
__device__ __forceinline__ double warp_ex_double(const float* __restrict__ xs,
                                                 const float* __restrict__ sup,
                                                 int n, int lane) {
    const float4* sr = (const float4*)(sup + (size_t)n * D_DIM);
    const float4* xr = (const float4*)xs;
    double dot = 0.0, ss = 0.0;
    #pragma unroll
    for (int u = 0; u < 8; u++) {
        float4 sv = sr[lane + u * 32];
        float4 xv = xr[lane + u * 32];
        dot += (double)xv.x * sv.x + (double)xv.y * sv.y
             + (double)xv.z * sv.z + (double)xv.w * sv.w;
        ss  += (double)sv.x * sv.x + (double)sv.y * sv.y
             + (double)sv.z * sv.z + (double)sv.w * sv.w;
    }
    double e = ss - 2.0 * dot;
    #pragma unroll
    for (int o = 16; o; o >>= 1) e += __shfl_xor_sync(0xffffffffu, e, o);
    return e;
}

__global__ void __launch_bounds__(256) refine_kernel(const float* __restrict__ x,
                                                     const float* __restrict__ sup) {
    const int b    = blockIdx.x;
    const int tid  = threadIdx.x;
    const int wid  = tid >> 5;
    const int lane = tid & 31;

    __shared__ float xs[D_DIM];
    __shared__ int sel_n[SEL_CAP];
    __shared__ int nsel;
    __shared__ double sel_v[SEL_CAP];
    __shared__ double wbest_v[8];
    __shared__ int    wbest_n[8];

    for (int i = tid; i < D_DIM / 4; i += 256)
        ((float4*)xs)[i] = ((const float4*)(x + (size_t)b * D_DIM))[i];
    if (tid == 0) nsel = 0;
    __syncthreads();

    const unsigned long long mk = g_minkey[b];
    const unsigned int qmin = (unsigned int)(mk >> 32);
    const unsigned int qthr = qmin + QMARGIN;

    // scan 50048 u8 scores (uint4 = 16 scores per load)
    const uint4* qrow = (const uint4*)(g_q8 + (size_t)b * N_PAD);
    for (int i = tid; i < N_PAD / 16; i += 256) {
        uint4 v = qrow[i];
        unsigned int w[4] = { v.x, v.y, v.z, v.w };
        #pragma unroll
        for (int j = 0; j < 4; j++) {
            #pragma unroll
            for (int byi = 0; byi < 4; byi++) {
                unsigned int q = (w[j] >> (byi * 8)) & 0xFFu;
                if (q <= qthr) {
                    int p = atomicAdd(&nsel, 1);
                    if (p < SEL_CAP) sel_n[p] = i * 16 + 4 * j + byi;
                }
            }
        }
    }
    __syncthreads();

    if (nsel <= SEL_CAP) {
        int ns = nsel;
        for (int i = wid; i < ns; i += 8) {
            int n = sel_n[i];
            double e = (n >= N_REAL) ? 1.0e300 : warp_ex_double(xs, sup, n, lane);
            if (lane == 0) sel_v[i] = e;
        }
        __syncthreads();
        if (tid == 0) {
            int best_n = (int)(unsigned int)mk;
            if (ns > 0) {
                double bv = 1.0e301;
                best_n = -1;
                for (int i = 0; i < ns; i++) {
                    int n = sel_n[i];
                    if (n >= N_REAL) continue;
                    if (sel_v[i] < bv || (sel_v[i] == bv && n < best_n)) {
                        bv = sel_v[i];
                        best_n = n;
                    }
                }
                if (best_n < 0) best_n = (int)(unsigned int)mk;
            }
            g_exidx[b] = best_n;
        }
    } else {
        // overflow fallback (never expected): full exact fp64 scan
        double bv = 1.0e301;
        int    bn = -1;
        for (int n = wid; n < N_REAL; n += 8) {
            double e = warp_ex_double(xs, sup, n, lane);
            if (lane == 0 && (e < bv || (e == bv && n < bn))) { bv = e; bn = n; }
        }
        if (lane == 0) { wbest_v[wid] = bv; wbest_n[wid] = bn; }
        __syncthreads();
        if (tid == 0) {
            double m = wbest_v[0]; int mn = wbest_n[0];
            for (int i = 1; i < 8; i++)
                if (wbest_v[i] < m || (wbest_v[i] == m && wbest_n[i] < mn)) {
                    m = wbest_v[i]; mn = wbest_n[i];
                }
            g_exidx[b] = (mn < 0) ? 0 : mn;
        }
    }
}

// ---------------- 4. one-hot output (float32) --------------------------------
__global__ void out_kernel(const int* __restrict__ labw,
                           float* __restrict__ out) {
    __shared__ int is64_sh;
    int tid = threadIdx.x;
    if (tid == 0) {
        int odd_nonzero = 0;
        #pragma unroll
        for (int i = 0; i < 128; i++) odd_nonzero |= labw[2 * i + 1];
        is64_sh = (odd_nonzero == 0) ? 1 : 0;
    }
    __syncthreads();
    int is64 = is64_sh;
    int b = blockIdx.x * 256 + tid;
    if (b >= M_TOTAL) return;
    unsigned int n = (unsigned int)g_exidx[b];
    if (n >= N_REAL) n = 0;
    int lab = is64 ? labw[2 * n] : labw[n];
    out[2 * b + 0] = (lab == 0) ? 1.0f : 0.0f;
    out[2 * b + 1] = (lab != 0) ? 1.0f : 0.0f;
}

// ---------------- eager module load ------------------------------------------
namespace {
struct ModuleWarm {
    ModuleWarm() {
        cudaFuncAttributes a;
        cudaFuncGetAttributes(&a, (const void*)gemm_kernel);
        cudaFuncGetAttributes(&a, (const void*)refine_kernel);
        cudaFuncGetAttributes(&a, (const void*)prep_x_kernel);
    }
};
ModuleWarm warm_;
}

// ---------------- launch ------------------------------------------------------
extern "C" void kernel_launch(void* const* d_in, const int* in_sizes, int n_in,
                              void* d_out, int out_size) {
    (void)out_size;
    static bool attr_done = false;
    if (!attr_done) {
        cudaFuncSetAttribute((const void*)gemm_kernel,
                             cudaFuncAttributeMaxDynamicSharedMemorySize,
                             SMEM_GEMM);
        attr_done = true;
    }

    const float* x   = (const float*)d_in[0];
    const float* sup = (const float*)d_in[1];
    const int*   lab = (const int*)d_in[2];
    if (n_in >= 3) {
        int i_big = 0, i_sml = 0;
        for (int i = 1; i < 3; i++) {
            if (in_sizes[i] > in_sizes[i_big]) i_big = i;
            if (in_sizes[i] < in_sizes[i_sml]) i_sml = i;
        }
        int i_mid = 3 - i_big - i_sml;
        sup = (const float*)d_in[i_big];
        x   = (const float*)d_in[i_mid];
        lab = (const int*)d_in[i_sml];
    }
    float* out = (float*)d_out;

    prep_x_kernel<<<M_TOTAL, 256>>>(x, out);
    prep_support_kernel<<<N_PAD, 256>>>(sup);
    dim3 gg(NUM_MT, NTILES);    // x = mt fast: 16 CTAs share each B tile in L2
    gemm_kernel<<<gg, 256, SMEM_GEMM>>>();
    refine_kernel<<<M_TOTAL, 256>>>(x, sup);
    out_kernel<<<8, 256>>>(lab, out);
}

// round 17
// speedup vs baseline: 1.0863x; 1.0863x over previous
#include <cuda_runtime.h>
#include <cuda_bf16.h>
#include <cstdint>

// ============================================================================
// kNN (1-NN, L2), round 17: R16 + fixed refine scan.
//   refine scan now uses __vcmpleu4 SIMD byte-compare with whole-uint4
//   early-out (~99.97% of 16-score blocks skip in ~9 ALU ops), and
//   __launch_bounds__(256,3) for 3 CTAs/SM of load MLP.
//   gemm/prep/out unchanged from R16 (u8 scores, cell 4.0, offset 384).
// ============================================================================

#define D_DIM   1024
#define M_TOTAL 2048
#define N_REAL  50000
#define N_PAD   50048
#define NTILES  391
#define MTILE   128
#define NTILE   128
#define NUM_MT  (M_TOTAL / MTILE)   // 16
#define KC      128                 // int8 elements per chunk = 128 B rows
#define NUM_KC  (D_DIM / KC)        // 8
#define NSTAGE  3

#define SCALE_Q   (6.5f / 127.0f)
#define SCALE_INV (127.0f / 6.5f)
#define SQ2       (SCALE_Q * SCALE_Q)

#define Q8OFF   384.0f              // u8 score quant: q=(score-384)*0.25
#define Q8SCALE 0.25f
#define QMARGIN 6                   // 24 score units (>= 16-unit noise margin)
#define SEL_CAP 256

#define ROW_B   144                 // 128 B data padded to 144 B
#define TILE_B  (128 * ROW_B)       // 18432
#define STAGE_B (2 * TILE_B)        // 36864
#define SMEM_GEMM (NSTAGE * STAGE_B + 512)   // 111104 B

// ---------------- device-global scratch --------------------------------------
__device__ __align__(16) signed char g_xq[(size_t)M_TOTAL * D_DIM];
__device__ __align__(16) signed char g_sq[(size_t)N_PAD * D_DIM];
__device__ float               g_s2[N_PAD];
__device__ __align__(16) unsigned char g_q8[(size_t)M_TOTAL * N_PAD];  // 102 MB
__device__ unsigned long long  g_minkey[M_TOTAL];
__device__ int                 g_exidx[M_TOTAL];

// ---------------- helpers ----------------------------------------------------
__device__ __forceinline__ uint32_t smem_u32(const void* p) {
    uint32_t a;
    asm("{ .reg .u64 t; cvta.to.shared.u64 t, %1; cvt.u32.u64 %0, t; }"
        : "=r"(a) : "l"(p));
    return a;
}
#define CP_ASYNC16(smem, gptr)                                               \
    asm volatile("cp.async.cg.shared.global [%0], [%1], 16;"                 \
                 :: "r"(smem), "l"(gptr) : "memory")
#define CP_COMMIT() asm volatile("cp.async.commit_group;" ::: "memory")
#define CP_WAIT(n)  asm volatile("cp.async.wait_group %0;" :: "n"(n) : "memory")

__device__ __forceinline__ void ldm_x4(uint32_t& r0, uint32_t& r1,
                                       uint32_t& r2, uint32_t& r3, uint32_t addr) {
    asm volatile("ldmatrix.sync.aligned.m8n8.x4.shared.b16 {%0,%1,%2,%3}, [%4];"
                 : "=r"(r0), "=r"(r1), "=r"(r2), "=r"(r3) : "r"(addr));
}
__device__ __forceinline__ void mma16832(int* c, uint32_t a0, uint32_t a1,
                                         uint32_t a2, uint32_t a3,
                                         uint32_t b0, uint32_t b1) {
    asm volatile(
        "mma.sync.aligned.m16n8k32.row.col.s32.s8.s8.s32 "
        "{%0,%1,%2,%3}, {%4,%5,%6,%7}, {%8,%9}, {%0,%1,%2,%3};"
        : "+r"(c[0]), "+r"(c[1]), "+r"(c[2]), "+r"(c[3])
        : "r"(a0), "r"(a1), "r"(a2), "r"(a3), "r"(b0), "r"(b1));
}
__device__ __forceinline__ unsigned int quant8(float score) {
    float q = (score - Q8OFF) * Q8SCALE;
    q = fminf(fmaxf(q, 0.0f), 255.0f);
    return (unsigned int)__float2uint_rn(q);
}
__device__ __forceinline__ int q8v(float v) {
    int q = __float2int_rn(v * SCALE_INV);
    return max(-127, min(127, q));
}
__device__ __forceinline__ unsigned int pack8(float a, float b, float c, float d) {
    return ((unsigned int)(q8v(a) & 0xFF))       |
           ((unsigned int)(q8v(b) & 0xFF) << 8)  |
           ((unsigned int)(q8v(c) & 0xFF) << 16) |
           ((unsigned int)(q8v(d) & 0xFF) << 24);
}

// ---------------- 1. prep (also inits minkey + output canary) ----------------
__global__ void prep_x_kernel(const float* __restrict__ x,
                              float* __restrict__ out) {
    int row = blockIdx.x;
    int tid = threadIdx.x;              // 256
    float4 v = ((const float4*)(x + (size_t)row * D_DIM))[tid];
    ((unsigned int*)(g_xq + (size_t)row * D_DIM))[tid] = pack8(v.x, v.y, v.z, v.w);
    if (tid == 0) {
        g_minkey[row] = ~0ull;
        out[2 * row + 0] = 7.0f;   // canary
        out[2 * row + 1] = 0.0f;
    }
}

__global__ void prep_support_kernel(const float* __restrict__ sup) {
    int row = blockIdx.x;               // 0..50047
    int tid = threadIdx.x;              // 256
    float acc = 0.0f;
    unsigned int pk = 0;
    if (row < N_REAL) {
        float4 v = ((const float4*)(sup + (size_t)row * D_DIM))[tid];
        acc = v.x * v.x + v.y * v.y + v.z * v.z + v.w * v.w;
        pk = pack8(v.x, v.y, v.z, v.w);
    }
    ((unsigned int*)(g_sq + (size_t)row * D_DIM))[tid] = pk;
    #pragma unroll
    for (int o = 16; o; o >>= 1) acc += __shfl_down_sync(0xffffffffu, acc, o);
    __shared__ float red[8];
    if ((tid & 31) == 0) red[tid >> 5] = acc;
    __syncthreads();
    if (tid == 0) {
        float t = 0.f;
        #pragma unroll
        for (int i = 0; i < 8; i++) t += red[i];
        g_s2[row] = (row < N_REAL) ? t : 3.0e38f;   // pad rows -> q=255
    }
}

// ---------------- 2. GEMM (int8, 3-stage cp.async, 1 barrier/chunk) ----------
__global__ void __launch_bounds__(256, 2) gemm_kernel() {
    extern __shared__ __align__(16) uint8_t sm[];
    float* s2sh = (float*)(sm + NSTAGE * STAGE_B);

    const int tid  = threadIdx.x;
    const int lane = tid & 31;
    const int wid  = tid >> 5;
    const int warp_m = wid & 1;
    const int warp_n = wid >> 1;

    const int mt   = blockIdx.x;
    const int tile = blockIdx.y;
    const int m_base = mt * MTILE;
    const int n_base = tile * NTILE;

    if (tid < NTILE) s2sh[tid] = g_s2[n_base + tid];

    const uint32_t smem_base = smem_u32(sm);

    // cp.async map: 128 rows x 8 16B-cols = 1024 chunks, 4/thread
    const int fr = tid >> 3;            // 0..31 (+32 per p)
    const int fc = tid & 7;
    const uint32_t w_off = (uint32_t)(fr * ROW_B + fc * 16);
    const signed char* gA0 = g_xq + (size_t)(m_base + fr) * D_DIM + fc * 16;
    const signed char* gB0 = g_sq + (size_t)(n_base + fr) * D_DIM + fc * 16;

    auto load_chunk = [&](int stage, int kc) {
        uint32_t sa = smem_base + (uint32_t)(stage * STAGE_B) + w_off;
        uint32_t sb = sa + TILE_B;
        int kb = kc * KC;
        #pragma unroll
        for (int p = 0; p < 4; p++) {
            CP_ASYNC16(sa + (uint32_t)(p * 32 * ROW_B),
                       gA0 + (size_t)(p * 32) * D_DIM + kb);
            CP_ASYNC16(sb + (uint32_t)(p * 32 * ROW_B),
                       gB0 + (size_t)(p * 32) * D_DIM + kb);
        }
    };

    const uint32_t a_lane_off =
        (uint32_t)((lane & 15) * ROW_B + (lane >> 4) * 16);
    const uint32_t b_lane_off =
        (uint32_t)(((((lane >> 4) & 1) * 8 + (lane & 7)) * ROW_B) +
                   (((lane >> 3) & 1) * 16));
    const uint32_t a_warp = (uint32_t)(warp_m * 64 * ROW_B) + a_lane_off;
    const uint32_t b_warp = (uint32_t)(TILE_B + warp_n * 32 * ROW_B) + b_lane_off;

    int acc[4][4][4];
    #pragma unroll
    for (int mi = 0; mi < 4; mi++)
        #pragma unroll
        for (int ni = 0; ni < 4; ni++)
            #pragma unroll
            for (int j = 0; j < 4; j++) acc[mi][ni][j] = 0;

    uint32_t afr[2][4][4];
    uint32_t bfr[2][4][2];

    auto ldfrag = [&](uint32_t a_base, uint32_t b_base, int ks, int slot) {
        #pragma unroll
        for (int mi = 0; mi < 4; mi++)
            ldm_x4(afr[slot][mi][0], afr[slot][mi][1],
                   afr[slot][mi][2], afr[slot][mi][3],
                   a_base + (uint32_t)(mi * 16 * ROW_B + ks * 32));
        #pragma unroll
        for (int nip = 0; nip < 2; nip++) {
            uint32_t r0, r1, r2, r3;
            ldm_x4(r0, r1, r2, r3,
                   b_base + (uint32_t)(nip * 16 * ROW_B + ks * 32));
            bfr[slot][nip * 2][0] = r0;     bfr[slot][nip * 2][1] = r1;
            bfr[slot][nip * 2 + 1][0] = r2; bfr[slot][nip * 2 + 1][1] = r3;
        }
    };

    // prologue: stages 0,1 hold chunks 0,1
    load_chunk(0, 0); CP_COMMIT();
    load_chunk(1, 1); CP_COMMIT();

    int stage = 0;
    for (int kc = 0; kc < NUM_KC; kc++) {
        CP_WAIT(1);          // chunk kc complete (kc+1 may be in flight)
        __syncthreads();     // publishes chunk kc AND retires buffer of kc-1

        if (kc + 2 < NUM_KC) load_chunk((stage + 2) % NSTAGE, kc + 2);
        CP_COMMIT();         // always commit (uniform wait semantics)

        uint32_t a_base = smem_base + (uint32_t)(stage * STAGE_B) + a_warp;
        uint32_t b_base = smem_base + (uint32_t)(stage * STAGE_B) + b_warp;

        ldfrag(a_base, b_base, 0, 0);
        #pragma unroll
        for (int ks = 0; ks < 4; ks++) {   // 4 x k32 = 128 K-elems
            int cur = ks & 1;
            if (ks < 3) ldfrag(a_base, b_base, ks + 1, cur ^ 1);
            #pragma unroll
            for (int mi = 0; mi < 4; mi++)
                #pragma unroll
                for (int ni = 0; ni < 4; ni++)
                    mma16832(acc[mi][ni],
                             afr[cur][mi][0], afr[cur][mi][1],
                             afr[cur][mi][2], afr[cur][mi][3],
                             bfr[cur][ni][0], bfr[cur][ni][1]);
        }
        stage = (stage + 1) % NSTAGE;
    }

    // ---- epilogue: u8 score store + per-row atomicMin ----------------------
    #pragma unroll
    for (int mi = 0; mi < 4; mi++) {
        int r_lo = m_base + warp_m * 64 + mi * 16 + (lane >> 2);
        int r_hi = r_lo + 8;
        unsigned long long k_lo = ~0ull, k_hi = ~0ull;
        #pragma unroll
        for (int ni = 0; ni < 4; ni++) {
            int ncl = warp_n * 32 + ni * 8 + 2 * (lane & 3);
            int ngl = n_base + ncl;
            float s20 = s2sh[ncl], s21 = s2sh[ncl + 1];
            unsigned int q00 = quant8(fmaf(-2.0f * SQ2, (float)acc[mi][ni][0], s20));
            unsigned int q01 = quant8(fmaf(-2.0f * SQ2, (float)acc[mi][ni][1], s21));
            unsigned int q10 = quant8(fmaf(-2.0f * SQ2, (float)acc[mi][ni][2], s20));
            unsigned int q11 = quant8(fmaf(-2.0f * SQ2, (float)acc[mi][ni][3], s21));
            *(unsigned short*)&g_q8[(size_t)r_lo * N_PAD + ngl] =
                (unsigned short)(q00 | (q01 << 8));
            *(unsigned short*)&g_q8[(size_t)r_hi * N_PAD + ngl] =
                (unsigned short)(q10 | (q11 << 8));
            unsigned long long t;
            t = ((unsigned long long)q00 << 32) | (unsigned int)ngl;       if (t < k_lo) k_lo = t;
            t = ((unsigned long long)q01 << 32) | (unsigned int)(ngl + 1); if (t < k_lo) k_lo = t;
            t = ((unsigned long long)q10 << 32) | (unsigned int)ngl;       if (t < k_hi) k_hi = t;
            t = ((unsigned long long)q11 << 32) | (unsigned int)(ngl + 1); if (t < k_hi) k_hi = t;
        }
        #pragma unroll
        for (int m = 1; m <= 2; m <<= 1) {
            unsigned long long o;
            o = __shfl_xor_sync(0xffffffffu, k_lo, m); if (o < k_lo) k_lo = o;
            o = __shfl_xor_sync(0xffffffffu, k_hi, m); if (o < k_hi) k_hi = o;
        }
        if ((lane & 3) == 0) {
            atomicMin(&g_minkey[r_lo], k_lo);
            atomicMin(&g_minkey[r_hi], k_hi);
        }
    }
}

// ---------------- 3. refine: SIMD u8 scan + fp64 decide ----------------------
__device__ __forceinline__ double warp_ex_double(const float* __restrict__ xs,
                                                 const float* __restrict__ sup,
                                                 int n, int lane) {
    const float4* sr = (const float4*)(sup + (size_t)n * D_DIM);
    const float4* xr = (const float4*)xs;
    double dot = 0.0, ss = 0.0;
    #pragma unroll
    for (int u = 0; u < 8; u++) {
        float4 sv = sr[lane + u * 32];
        float4 xv = xr[lane + u * 32];
        dot += (double)xv.x * sv.x + (double)xv.y * sv.y
             + (double)xv.z * sv.z + (double)xv.w * sv.w;
        ss  += (double)sv.x * sv.x + (double)sv.y * sv.y
             + (double)sv.z * sv.z + (double)sv.w * sv.w;
    }
    double e = ss - 2.0 * dot;
    #pragma unroll
    for (int o = 16; o; o >>= 1) e += __shfl_xor_sync(0xffffffffu, e, o);
    return e;
}

__global__ void __launch_bounds__(256, 3) refine_kernel(const float* __restrict__ x,
                                                        const float* __restrict__ sup) {
    const int b    = blockIdx.x;
    const int tid  = threadIdx.x;
    const int wid  = tid >> 5;
    const int lane = tid & 31;

    __shared__ float xs[D_DIM];
    __shared__ int sel_n[SEL_CAP];
    __shared__ int nsel;
    __shared__ double sel_v[SEL_CAP];
    __shared__ double wbest_v[8];
    __shared__ int    wbest_n[8];

    for (int i = tid; i < D_DIM / 4; i += 256)
        ((float4*)xs)[i] = ((const float4*)(x + (size_t)b * D_DIM))[i];
    if (tid == 0) nsel = 0;
    __syncthreads();

    const unsigned long long mk = g_minkey[b];
    const unsigned int qmin = (unsigned int)(mk >> 32);
    unsigned int qthr = qmin + QMARGIN;
    if (qthr > 255u) qthr = 255u;
    const unsigned int thrb = qthr * 0x01010101u;

    // SIMD scan: 16 u8 scores per uint4; whole-block early-out via vcmpleu4.
    const uint4* qrow = (const uint4*)(g_q8 + (size_t)b * N_PAD);
    for (int i = tid; i < N_PAD / 16; i += 256) {
        uint4 v = qrow[i];
        unsigned int m0 = __vcmpleu4(v.x, thrb);
        unsigned int m1 = __vcmpleu4(v.y, thrb);
        unsigned int m2 = __vcmpleu4(v.z, thrb);
        unsigned int m3 = __vcmpleu4(v.w, thrb);
        if ((m0 | m1 | m2 | m3) == 0u) continue;   // 99.97% path
        unsigned int m[4] = { m0, m1, m2, m3 };
        #pragma unroll
        for (int j = 0; j < 4; j++) {
            if (m[j] == 0u) continue;
            #pragma unroll
            for (int byi = 0; byi < 4; byi++) {
                if ((m[j] >> (byi * 8)) & 1u) {
                    int p = atomicAdd(&nsel, 1);
                    if (p < SEL_CAP) sel_n[p] = i * 16 + 4 * j + byi;
                }
            }
        }
    }
    __syncthreads();

    if (nsel <= SEL_CAP) {
        int ns = nsel;
        for (int i = wid; i < ns; i += 8) {
            int n = sel_n[i];
            double e = (n >= N_REAL) ? 1.0e300 : warp_ex_double(xs, sup, n, lane);
            if (lane == 0) sel_v[i] = e;
        }
        __syncthreads();
        if (tid == 0) {
            int best_n = (int)(unsigned int)mk;
            if (ns > 0) {
                double bv = 1.0e301;
                best_n = -1;
                for (int i = 0; i < ns; i++) {
                    int n = sel_n[i];
                    if (n >= N_REAL) continue;
                    if (sel_v[i] < bv || (sel_v[i] == bv && n < best_n)) {
                        bv = sel_v[i];
                        best_n = n;
                    }
                }
                if (best_n < 0) best_n = (int)(unsigned int)mk;
            }
            g_exidx[b] = best_n;
        }
    } else {
        // overflow fallback (never expected): full exact fp64 scan
        double bv = 1.0e301;
        int    bn = -1;
        for (int n = wid; n < N_REAL; n += 8) {
            double e = warp_ex_double(xs, sup, n, lane);
            if (lane == 0 && (e < bv || (e == bv && n < bn))) { bv = e; bn = n; }
        }
        if (lane == 0) { wbest_v[wid] = bv; wbest_n[wid] = bn; }
        __syncthreads();
        if (tid == 0) {
            double m = wbest_v[0]; int mn = wbest_n[0];
            for (int i = 1; i < 8; i++)
                if (wbest_v[i] < m || (wbest_v[i] == m && wbest_n[i] < mn)) {
                    m = wbest_v[i]; mn = wbest_n[i];
                }
            g_exidx[b] = (mn < 0) ? 0 : mn;
        }
    }
}

// ---------------- 4. one-hot output (float32) --------------------------------
__global__ void out_kernel(const int* __restrict__ labw,
                           float* __restrict__ out) {
    __shared__ int is64_sh;
    int tid = threadIdx.x;
    if (tid == 0) {
        int odd_nonzero = 0;
        #pragma unroll
        for (int i = 0; i < 128; i++) odd_nonzero |= labw[2 * i + 1];
        is64_sh = (odd_nonzero == 0) ? 1 : 0;
    }
    __syncthreads();
    int is64 = is64_sh;
    int b = blockIdx.x * 256 + tid;
    if (b >= M_TOTAL) return;
    unsigned int n = (unsigned int)g_exidx[b];
    if (n >= N_REAL) n = 0;
    int lab = is64 ? labw[2 * n] : labw[n];
    out[2 * b + 0] = (lab == 0) ? 1.0f : 0.0f;
    out[2 * b + 1] = (lab != 0) ? 1.0f : 0.0f;
}

// ---------------- eager module load ------------------------------------------
namespace {
struct ModuleWarm {
    ModuleWarm() {
        cudaFuncAttributes a;
        cudaFuncGetAttributes(&a, (const void*)gemm_kernel);
        cudaFuncGetAttributes(&a, (const void*)refine_kernel);
        cudaFuncGetAttributes(&a, (const void*)prep_x_kernel);
    }
};
ModuleWarm warm_;
}

// ---------------- launch ------------------------------------------------------
extern "C" void kernel_launch(void* const* d_in, const int* in_sizes, int n_in,
                              void* d_out, int out_size) {
    (void)out_size;
    static bool attr_done = false;
    if (!attr_done) {
        cudaFuncSetAttribute((const void*)gemm_kernel,
                             cudaFuncAttributeMaxDynamicSharedMemorySize,
                             SMEM_GEMM);
        attr_done = true;
    }

    const float* x   = (const float*)d_in[0];
    const float* sup = (const float*)d_in[1];
    const int*   lab = (const int*)d_in[2];
    if (n_in >= 3) {
        int i_big = 0, i_sml = 0;
        for (int i = 1; i < 3; i++) {
            if (in_sizes[i] > in_sizes[i_big]) i_big = i;
            if (in_sizes[i] < in_sizes[i_sml]) i_sml = i;
        }
        int i_mid = 3 - i_big - i_sml;
        sup = (const float*)d_in[i_big];
        x   = (const float*)d_in[i_mid];
        lab = (const int*)d_in[i_sml];
    }
    float* out = (float*)d_out;

    prep_x_kernel<<<M_TOTAL, 256>>>(x, out);
    prep_support_kernel<<<N_PAD, 256>>>(sup);
    dim3 gg(NUM_MT, NTILES);    // x = mt fast: 16 CTAs share each B tile in L2
    gemm_kernel<<<gg, 256, SMEM_GEMM>>>();
    refine_kernel<<<M_TOTAL, 256>>>(x, sup);
    out_kernel<<<8, 256>>>(lab, out);
}